// round 5
// baseline (speedup 1.0000x reference)
#include <cuda_runtime.h>

// ContrastiveLearningLoss: out = sum_i c_i * d_i + exp(d_i),
//   d_i = dot(z_a[i], z_b[i]),  c_i = n-3 for i<n-1, n-2 for i=n-1.
// Single-kernel HBM-bound streaming reduction (128 MiB read),
// last-block deterministic final reduce (no second launch).

#define D_DIM      256
#define NBLOCKS    2048
#define NTHREADS   256
#define WARPS_PER_BLOCK (NTHREADS / 32)

__device__ double       g_partials[NBLOCKS];
__device__ unsigned int g_ticket;   // zero-initialized; last block resets it

__device__ __forceinline__ float warp_sum(float s)
{
    #pragma unroll
    for (int off = 16; off > 0; off >>= 1)
        s += __shfl_xor_sync(0xffffffffu, s, off);
    return s;
}

__device__ __forceinline__ float row_partial(const float4* __restrict__ a,
                                             const float4* __restrict__ b,
                                             int lane)
{
    float4 a0 = a[lane];
    float4 b0 = b[lane];
    float4 a1 = a[lane + 32];
    float4 b1 = b[lane + 32];
    return a0.x * b0.x + a0.y * b0.y + a0.z * b0.z + a0.w * b0.w
         + a1.x * b1.x + a1.y * b1.y + a1.z * b1.z + a1.w * b1.w;
}

__global__ __launch_bounds__(NTHREADS)
void cl_loss_kernel(const float* __restrict__ za,
                    const float* __restrict__ zb,
                    float* __restrict__ out,
                    int n)
{
    const int warp = threadIdx.x >> 5;
    const int lane = threadIdx.x & 31;
    const int nwarps = gridDim.x * WARPS_PER_BLOCK;   // 16384

    double acc = 0.0;

    // Each warp owns rows {w, w+S, w+2S, w+3S}; process 2 rows per iteration
    // so 16 independent LDG.128 are in flight before any shuffle reduce.
    int row = blockIdx.x * WARPS_PER_BLOCK + warp;
    for (; row + nwarps < n; row += 2 * nwarps) {
        const int r0 = row;
        const int r1 = row + nwarps;
        const float4* a0p = reinterpret_cast<const float4*>(za + (size_t)r0 * D_DIM);
        const float4* b0p = reinterpret_cast<const float4*>(zb + (size_t)r0 * D_DIM);
        const float4* a1p = reinterpret_cast<const float4*>(za + (size_t)r1 * D_DIM);
        const float4* b1p = reinterpret_cast<const float4*>(zb + (size_t)r1 * D_DIM);

        float s0 = row_partial(a0p, b0p, lane);
        float s1 = row_partial(a1p, b1p, lane);

        s0 = warp_sum(s0);
        s1 = warp_sum(s1);

        if (lane == 0) {
            double c0 = (r0 == n - 1) ? (double)(n - 2) : (double)(n - 3);
            double c1 = (r1 == n - 1) ? (double)(n - 2) : (double)(n - 3);
            acc += c0 * (double)s0 + (double)expf(s0)
                 + c1 * (double)s1 + (double)expf(s1);
        }
    }
    // tail (at most one row)
    for (; row < n; row += nwarps) {
        const float4* ap = reinterpret_cast<const float4*>(za + (size_t)row * D_DIM);
        const float4* bp = reinterpret_cast<const float4*>(zb + (size_t)row * D_DIM);
        float s = warp_sum(row_partial(ap, bp, lane));
        if (lane == 0) {
            double c = (row == n - 1) ? (double)(n - 2) : (double)(n - 3);
            acc += c * (double)s + (double)expf(s);
        }
    }

    // Block-level partial
    __shared__ double sm[WARPS_PER_BLOCK];
    __shared__ bool   s_last;
    if (lane == 0) sm[warp] = acc;
    __syncthreads();

    if (threadIdx.x == 0) {
        double t = 0.0;
        #pragma unroll
        for (int i = 0; i < WARPS_PER_BLOCK; ++i) t += sm[i];
        g_partials[blockIdx.x] = t;
        __threadfence();
        unsigned int tk = atomicAdd(&g_ticket, 1u);
        s_last = (tk == (unsigned int)(gridDim.x - 1));
    }
    __syncthreads();

    // Last block: deterministic final reduce of 2048 partials (L2-hot).
    if (s_last) {
        __shared__ double sm2[NTHREADS];
        double t = 0.0;
        for (int i = threadIdx.x; i < NBLOCKS; i += NTHREADS)
            t += g_partials[i];                    // fixed order -> deterministic
        sm2[threadIdx.x] = t;
        __syncthreads();
        #pragma unroll
        for (int s = NTHREADS / 2; s > 0; s >>= 1) {
            if (threadIdx.x < s) sm2[threadIdx.x] += sm2[threadIdx.x + s];
            __syncthreads();
        }
        if (threadIdx.x == 0) {
            out[0] = (float)sm2[0];
            g_ticket = 0;                          // reset for next graph replay
        }
    }
}

extern "C" void kernel_launch(void* const* d_in, const int* in_sizes, int n_in,
                              void* d_out, int out_size)
{
    const float* za = (const float*)d_in[0];
    const float* zb = (const float*)d_in[1];
    float* out = (float*)d_out;

    const int n = in_sizes[0] / D_DIM;  // 65536

    cl_loss_kernel<<<NBLOCKS, NTHREADS>>>(za, zb, out, n);
}

// round 6
// speedup vs baseline: 1.2636x; 1.2636x over previous
#include <cuda_runtime.h>

// ContrastiveLearningLoss: out = sum_i c_i * d_i + exp(d_i),
//   d_i = dot(z_a[i], z_b[i]),  c_i = n-3 for i<n-1, n-2 for i=n-1.
// Single-kernel HBM-bound streaming reduction (128 MiB read).
// 1 row per warp-iteration (MLP_p1=8, avoids L1tex-queue spread),
// 1024 blocks -> 8 rows/warp, one wave, long T_CTA.

#define D_DIM      256
#define NBLOCKS    1024
#define NTHREADS   256
#define WARPS_PER_BLOCK (NTHREADS / 32)

__device__ double       g_partials[NBLOCKS];
__device__ unsigned int g_ticket;   // zero-initialized; last block resets it

__device__ __forceinline__ float warp_sum(float s)
{
    #pragma unroll
    for (int off = 16; off > 0; off >>= 1)
        s += __shfl_xor_sync(0xffffffffu, s, off);
    return s;
}

__global__ __launch_bounds__(NTHREADS)
void cl_loss_kernel(const float* __restrict__ za,
                    const float* __restrict__ zb,
                    float* __restrict__ out,
                    int n)
{
    const int warp = threadIdx.x >> 5;
    const int lane = threadIdx.x & 31;
    const int nwarps = gridDim.x * WARPS_PER_BLOCK;   // 8192

    double acc = 0.0;

    // One row per iteration: 8 independent LDG.128 in flight, then reduce.
    for (int row = blockIdx.x * WARPS_PER_BLOCK + warp; row < n;
         row += nwarps) {
        const float4* __restrict__ a =
            reinterpret_cast<const float4*>(za + (size_t)row * D_DIM);
        const float4* __restrict__ b =
            reinterpret_cast<const float4*>(zb + (size_t)row * D_DIM);

        float4 a0 = a[lane];
        float4 b0 = b[lane];
        float4 a1 = a[lane + 32];
        float4 b1 = b[lane + 32];

        float s = a0.x * b0.x + a0.y * b0.y + a0.z * b0.z + a0.w * b0.w
                + a1.x * b1.x + a1.y * b1.y + a1.z * b1.z + a1.w * b1.w;

        s = warp_sum(s);

        if (lane == 0) {
            double coeff = (row == n - 1) ? (double)(n - 2) : (double)(n - 3);
            acc += coeff * (double)s + (double)expf(s);
        }
    }

    // Block-level partial
    __shared__ double sm[WARPS_PER_BLOCK];
    __shared__ bool   s_last;
    if (lane == 0) sm[warp] = acc;
    __syncthreads();

    if (threadIdx.x == 0) {
        double t = 0.0;
        #pragma unroll
        for (int i = 0; i < WARPS_PER_BLOCK; ++i) t += sm[i];
        g_partials[blockIdx.x] = t;
        __threadfence();
        unsigned int tk = atomicAdd(&g_ticket, 1u);
        s_last = (tk == (unsigned int)(gridDim.x - 1));
    }
    __syncthreads();

    // Last block: deterministic final reduce of 1024 partials (L2-hot).
    if (s_last) {
        __shared__ double sm2[NTHREADS];
        double t = 0.0;
        for (int i = threadIdx.x; i < NBLOCKS; i += NTHREADS)
            t += g_partials[i];                    // fixed order -> deterministic
        sm2[threadIdx.x] = t;
        __syncthreads();
        #pragma unroll
        for (int s = NTHREADS / 2; s > 0; s >>= 1) {
            if (threadIdx.x < s) sm2[threadIdx.x] += sm2[threadIdx.x + s];
            __syncthreads();
        }
        if (threadIdx.x == 0) {
            out[0] = (float)sm2[0];
            g_ticket = 0;                          // reset for next graph replay
        }
    }
}

extern "C" void kernel_launch(void* const* d_in, const int* in_sizes, int n_in,
                              void* d_out, int out_size)
{
    const float* za = (const float*)d_in[0];
    const float* zb = (const float*)d_in[1];
    float* out = (float*)d_out;

    const int n = in_sizes[0] / D_DIM;  // 65536

    cl_loss_kernel<<<NBLOCKS, NTHREADS>>>(za, zb, out, n);
}